// round 9
// baseline (speedup 1.0000x reference)
#include <cuda_runtime.h>

// Shapes: seq=64 steps (orig B), only batch-row t=255 of T=256 matters.
#define STEPS 64
#define HID   1024
#define G4    4096
#define TT    256
#define DD    1024
#define CC    27
#define NB    128          // persistent CTAs (1/SM)
#define SENT  0xFFC0DEADu  // NaN payload: unreachable output bit pattern

typedef unsigned long long ull;
typedef unsigned int uint;

// ---- scratch (device globals; no allocation) ----
__device__ __align__(16) float g_h1[STEPS * HID];
__device__ __align__(16) float g_h2[STEPS * HID];
__device__ __align__(16) float g_z [STEPS * 512];

__global__ void reset_kernel() {
    int i = blockIdx.x * 256 + threadIdx.x;   // 256*256 = 65536 = STEPS*HID
    ((uint*)g_h1)[i] = SENT;
    ((uint*)g_h2)[i] = SENT;
    if (i < STEPS * 512) ((uint*)g_z)[i] = SENT;
}

__device__ __forceinline__ float sigf(float x)     { return 1.0f / (1.0f + __expf(-x)); }
__device__ __forceinline__ float tanhfast(float x) { return 2.0f / (1.0f + __expf(-2.0f * x)) - 1.0f; }

__device__ __forceinline__ ull fma2(ull a, ull b, ull c) {
    ull d;
    asm("fma.rn.f32x2 %0, %1, %2, %3;" : "=l"(d) : "l"(a), "l"(b), "l"(c));
    return d;
}
__device__ __forceinline__ float2 unpack2(ull v) {
    float2 f;
    asm("mov.b64 {%0, %1}, %2;" : "=f"(f.x), "=f"(f.y) : "l"(v));
    return f;
}
// morally-strong relaxed atomics (gpu scope) for all racing accesses
__device__ __forceinline__ ull ld_relaxed_b64(const ull* p) {
    ull v;
    asm volatile("ld.relaxed.gpu.global.b64 %0, [%1];" : "=l"(v) : "l"(p) : "memory");
    return v;
}
__device__ __forceinline__ void st_relaxed_f32(float* p, float v) {
    asm volatile("st.relaxed.gpu.global.f32 [%0], %1;" :: "l"(p), "f"(v) : "memory");
}
__device__ __forceinline__ ull poll_b64(const ull* p) {
    ull v; uint2 u;
    do { v = ld_relaxed_b64(p); u = *(uint2*)&v; } while (u.x == SENT || u.y == SENT);
    return v;
}

// ============================================================
// ONE persistent kernel: G0 -> rec0 -> G1 -> rec1 -> fc1 -> fc2
// 128 CTAs x 512 threads. CTA r owns gate rows {g*1024 + r*8 + u}.
// Warp w (16/CTA): gate g=w&3, unit pair jh=w>>2, rows rowbase,rowbase+1.
// ============================================================
__global__ __launch_bounds__(512, 1)
void mega_k(const float* __restrict__ x,
            const float* __restrict__ Wih0, const float* __restrict__ Whh0,
            const float* __restrict__ bih0, const float* __restrict__ bhh0,
            const float* __restrict__ Wih1, const float* __restrict__ Whh1,
            const float* __restrict__ bih1, const float* __restrict__ bhh1,
            const float* __restrict__ W1,   const float* __restrict__ b1,
            const float* __restrict__ W2,   const float* __restrict__ b2,
            float* __restrict__ out)
{
    __shared__ __align__(16) float hsh[HID];          // rec h staging (4KB)
    __shared__ __align__(16) float xstage[4 * HID];   // G/FC staging (16KB)
    __shared__ __align__(16) float xgs[STEPS * 32];   // CTA-local xg (8KB)
    __shared__ __align__(16) float zsh[512];          // fc2 staging
    __shared__ float graw[32], gact[32];

    const int r    = blockIdx.x;
    const int t    = threadIdx.x;
    const int lane = t & 31;
    const int w    = t >> 5;
    const int g    = w & 3;
    const int jh   = w >> 2;
    const int rowbase = (g << 10) + (r << 3) + (jh << 1);

    ull w0[16], w1[16];   // 2 weight rows, packed f32x2, reloaded per phase

    // ======================= Phase G0: xg0 -> xgs =======================
#pragma unroll
    for (int p = 0; p < 16; p++) {
        long o = (long)rowbase * 1024 + p * 64 + lane * 2;
        w0[p] = *(const ull*)(Wih0 + o);
        w1[p] = *(const ull*)(Wih0 + o + 1024);
    }
    {
        float2 gb = make_float2(0.f, 0.f);
        if (lane == 0) {
            gb.x = bih0[rowbase]     + bhh0[rowbase];
            gb.y = bih0[rowbase + 1] + bhh0[rowbase + 1];
        }
        for (int sb = 0; sb < 16; sb++) {
#pragma unroll
            for (int q = 0; q < 4; q++) {
                const ull* sp = (const ull*)(x + (long)(sb * 4 + q) * (TT * DD) + 255L * DD);
                ((ull*)xstage)[q * 512 + t] = sp[t];
            }
            __syncthreads();
            ull A[8];
#pragma unroll
            for (int j = 0; j < 8; j++) A[j] = 0ull;
#pragma unroll
            for (int p = 0; p < 16; p++) {
#pragma unroll
                for (int q = 0; q < 4; q++) {
                    ull hv = ((const ull*)xstage)[q * 512 + p * 32 + lane];
                    A[q * 2 + 0] = fma2(w0[p], hv, A[q * 2 + 0]);
                    A[q * 2 + 1] = fma2(w1[p], hv, A[q * 2 + 1]);
                }
            }
            float a[8];
#pragma unroll
            for (int j = 0; j < 8; j++) { float2 f = unpack2(A[j]); a[j] = f.x + f.y; }
#pragma unroll
            for (int o = 16; o > 0; o >>= 1)
#pragma unroll
                for (int j = 0; j < 8; j++) a[j] += __shfl_down_sync(0xffffffffu, a[j], o);
            if (lane == 0) {
#pragma unroll
                for (int q = 0; q < 4; q++) {
                    xgs[(sb * 4 + q) * 32 + w * 2 + 0] = a[q * 2 + 0] + gb.x;
                    xgs[(sb * 4 + q) * 32 + w * 2 + 1] = a[q * 2 + 1] + gb.y;
                }
            }
            __syncthreads();   // protect xstage reuse
        }
    }

    // ======================= rec0: layer-1 recurrence =======================
#pragma unroll
    for (int p = 0; p < 16; p++) {
        long o = (long)rowbase * 1024 + p * 64 + lane * 2;
        w0[p] = *(const ull*)(Whh0 + o);
        w1[p] = *(const ull*)(Whh0 + o + 1024);
    }
    {
        float creg = 0.0f;
        float* hseq = g_h1;
        for (int s = 0; s < STEPS; s++) {
            float2 xq = make_float2(0.f, 0.f);
            if (lane == 0) xq = *(const float2*)&xgs[s * 32 + w * 2];

            float a0 = 0.f, a1 = 0.f;
            if (s > 0) {
                ull hv = poll_b64((const ull*)(hseq + (s - 1) * HID) + t);
                ((ull*)hsh)[t] = hv;
                __syncthreads();   // staging sync
                ull acc0 = 0ull, acc1 = 0ull;
#pragma unroll
                for (int p = 0; p < 16; p++) {
                    ull h2 = *(const ull*)&hsh[p * 64 + lane * 2];
                    acc0 = fma2(w0[p], h2, acc0);
                    acc1 = fma2(w1[p], h2, acc1);
                }
                float2 f0 = unpack2(acc0), f1 = unpack2(acc1);
                a0 = f0.x + f0.y; a1 = f1.x + f1.y;
            }
#pragma unroll
            for (int o = 16; o > 0; o >>= 1) {
                a0 += __shfl_down_sync(0xffffffffu, a0, o);
                a1 += __shfl_down_sync(0xffffffffu, a1, o);
            }
            if (lane == 0) {
                graw[(jh * 2 + 0) * 4 + g] = a0 + xq.x;
                graw[(jh * 2 + 1) * 4 + g] = a1 + xq.y;
            }
            __syncthreads();   // (A)
            if (w == 0) {
                float v = graw[lane];
                gact[lane] = ((lane & 3) == 2) ? tanhfast(v) : sigf(v);
                __syncwarp();
                if (lane < 8) {
                    float iv = gact[lane * 4 + 0], fv = gact[lane * 4 + 1];
                    float gv = gact[lane * 4 + 2], ov = gact[lane * 4 + 3];
                    creg = fmaf(fv, creg, iv * gv);
                    st_relaxed_f32(&hseq[s * HID + r * 8 + lane], ov * tanhfast(creg));
                }
            }
            // no end-of-step sync (ordering via poll-gating; proven in R8)
        }
    }

    // ======================= Phase G1: xg1 from g_h1 =======================
#pragma unroll
    for (int p = 0; p < 16; p++) {
        long o = (long)rowbase * 1024 + p * 64 + lane * 2;
        w0[p] = *(const ull*)(Wih1 + o);
        w1[p] = *(const ull*)(Wih1 + o + 1024);
    }
    {
        float2 gb = make_float2(0.f, 0.f);
        if (lane == 0) {
            gb.x = bih1[rowbase]     + bhh1[rowbase];
            gb.y = bih1[rowbase + 1] + bhh1[rowbase + 1];
        }
        for (int sb = 0; sb < 16; sb++) {
#pragma unroll
            for (int q = 0; q < 4; q++)   // sentinel-checked: absorbs rec0 skew
                ((ull*)xstage)[q * 512 + t] =
                    poll_b64((const ull*)g_h1 + (long)(sb * 4 + q) * 512 + t);
            __syncthreads();   // also orders: all threads past rec0's xgs reads
            ull A[8];
#pragma unroll
            for (int j = 0; j < 8; j++) A[j] = 0ull;
#pragma unroll
            for (int p = 0; p < 16; p++) {
#pragma unroll
                for (int q = 0; q < 4; q++) {
                    ull hv = ((const ull*)xstage)[q * 512 + p * 32 + lane];
                    A[q * 2 + 0] = fma2(w0[p], hv, A[q * 2 + 0]);
                    A[q * 2 + 1] = fma2(w1[p], hv, A[q * 2 + 1]);
                }
            }
            float a[8];
#pragma unroll
            for (int j = 0; j < 8; j++) { float2 f = unpack2(A[j]); a[j] = f.x + f.y; }
#pragma unroll
            for (int o = 16; o > 0; o >>= 1)
#pragma unroll
                for (int j = 0; j < 8; j++) a[j] += __shfl_down_sync(0xffffffffu, a[j], o);
            if (lane == 0) {
#pragma unroll
                for (int q = 0; q < 4; q++) {
                    xgs[(sb * 4 + q) * 32 + w * 2 + 0] = a[q * 2 + 0] + gb.x;
                    xgs[(sb * 4 + q) * 32 + w * 2 + 1] = a[q * 2 + 1] + gb.y;
                }
            }
            __syncthreads();
        }
    }

    // ======================= rec1: layer-2 recurrence =======================
#pragma unroll
    for (int p = 0; p < 16; p++) {
        long o = (long)rowbase * 1024 + p * 64 + lane * 2;
        w0[p] = *(const ull*)(Whh1 + o);
        w1[p] = *(const ull*)(Whh1 + o + 1024);
    }
    {
        float creg = 0.0f;
        float* hseq = g_h2;
        for (int s = 0; s < STEPS; s++) {
            float2 xq = make_float2(0.f, 0.f);
            if (lane == 0) xq = *(const float2*)&xgs[s * 32 + w * 2];

            float a0 = 0.f, a1 = 0.f;
            if (s > 0) {
                ull hv = poll_b64((const ull*)(hseq + (s - 1) * HID) + t);
                ((ull*)hsh)[t] = hv;
                __syncthreads();
                ull acc0 = 0ull, acc1 = 0ull;
#pragma unroll
                for (int p = 0; p < 16; p++) {
                    ull h2 = *(const ull*)&hsh[p * 64 + lane * 2];
                    acc0 = fma2(w0[p], h2, acc0);
                    acc1 = fma2(w1[p], h2, acc1);
                }
                float2 f0 = unpack2(acc0), f1 = unpack2(acc1);
                a0 = f0.x + f0.y; a1 = f1.x + f1.y;
            }
#pragma unroll
            for (int o = 16; o > 0; o >>= 1) {
                a0 += __shfl_down_sync(0xffffffffu, a0, o);
                a1 += __shfl_down_sync(0xffffffffu, a1, o);
            }
            if (lane == 0) {
                graw[(jh * 2 + 0) * 4 + g] = a0 + xq.x;
                graw[(jh * 2 + 1) * 4 + g] = a1 + xq.y;
            }
            __syncthreads();
            if (w == 0) {
                float v = graw[lane];
                gact[lane] = ((lane & 3) == 2) ? tanhfast(v) : sigf(v);
                __syncwarp();
                if (lane < 8) {
                    float iv = gact[lane * 4 + 0], fv = gact[lane * 4 + 1];
                    float gv = gact[lane * 4 + 2], ov = gact[lane * 4 + 3];
                    creg = fmaf(fv, creg, iv * gv);
                    st_relaxed_f32(&hseq[s * HID + r * 8 + lane], ov * tanhfast(creg));
                }
            }
        }
    }

    // ======================= fc1: z rows [4r, 4r+4) for all s =======================
    for (int sb = 0; sb < 16; sb++) {
#pragma unroll
        for (int q = 0; q < 4; q++)   // sentinel-checked h2 staging
            ((ull*)xstage)[q * 512 + t] =
                poll_b64((const ull*)g_h2 + (long)(sb * 4 + q) * 512 + t);
        __syncthreads();
        {
            const int rowi = w & 3;
            const int q    = w >> 2;
            const int row  = r * 4 + rowi;
            const int s    = sb * 4 + q;
            const ull* W1row = (const ull*)(W1 + (long)row * 1024);
            ull acc = 0ull;
#pragma unroll
            for (int p = 0; p < 16; p++) {
                int k64 = p * 32 + lane;
                acc = fma2(__ldg(W1row + k64), ((const ull*)xstage)[q * 512 + k64], acc);
            }
            float2 f = unpack2(acc);
            float a = f.x + f.y;
#pragma unroll
            for (int o = 16; o > 0; o >>= 1) a += __shfl_down_sync(0xffffffffu, a, o);
            if (lane == 0)
                st_relaxed_f32(&g_z[s * 512 + row], fmaxf(a + b1[row], 0.f));
        }
        __syncthreads();
    }

    // ======================= fc2: CTA r<64 owns step s=r =======================
    if (r < STEPS) {
        const int s = r;
        if (t < 256) {
            ull v = poll_b64((const ull*)g_z + (long)s * 256 + t);
            ((ull*)zsh)[t] = v;
        }
        __syncthreads();
        for (int c = w; c < CC; c += 16) {
            float acc = 0.f;
#pragma unroll
            for (int k = 0; k < 16; k++)
                acc = fmaf(zsh[k * 32 + lane], W2[c * 512 + k * 32 + lane], acc);
#pragma unroll
            for (int o = 16; o > 0; o >>= 1)
                acc += __shfl_down_sync(0xffffffffu, acc, o);
            if (lane == 0) out[s * CC + c] = acc + b2[c];
        }
    }
}

// ============================================================
extern "C" void kernel_launch(void* const* d_in, const int* in_sizes, int n_in,
                              void* d_out, int out_size)
{
    const float* x    = (const float*)d_in[0];
    const float* Wih0 = (const float*)d_in[1];
    const float* Whh0 = (const float*)d_in[2];
    const float* bih0 = (const float*)d_in[3];
    const float* bhh0 = (const float*)d_in[4];
    const float* Wih1 = (const float*)d_in[5];
    const float* Whh1 = (const float*)d_in[6];
    const float* bih1 = (const float*)d_in[7];
    const float* bhh1 = (const float*)d_in[8];
    const float* W1   = (const float*)d_in[9];
    const float* b1   = (const float*)d_in[10];
    const float* W2   = (const float*)d_in[11];
    const float* b2   = (const float*)d_in[12];
    float* out = (float*)d_out;

    reset_kernel<<<256, 256>>>();   // sentinel-fill g_h1/g_h2/g_z
    mega_k<<<NB, 512>>>(x, Wih0, Whh0, bih0, bhh0,
                        Wih1, Whh1, bih1, bhh1,
                        W1, b1, W2, b2, out);
}

// round 10
// speedup vs baseline: 1.0629x; 1.0629x over previous
#include <cuda_runtime.h>

// Shapes: seq=64 steps (orig B), only batch-row t=255 of T=256 matters.
#define STEPS 64
#define HID   1024
#define G4    4096
#define TT    256
#define DD    1024
#define CC    27
#define NB    128          // recurrence CTAs (1/SM, co-resident)
#define NCH   16           // GEMM K-split chunks
#define KC    64           // k per chunk
#define SENT  0xFFC0DEADu  // NaN payload: impossible LSTM output bit pattern

typedef unsigned long long ull;
typedef unsigned int uint;

// ---- scratch (device globals; no allocation) ----
__device__ __align__(16) float g_xgp[(long)NCH * STEPS * G4];  // gate-preact partials
__device__ __align__(16) float g_h1 [STEPS * HID];
__device__ __align__(16) float g_h2 [STEPS * HID];
__device__ __align__(16) float g_zp [NCH * STEPS * 512];       // fc1 partials

__global__ void reset_kernel() {
    int i = blockIdx.x * 256 + threadIdx.x;   // 256x256 = 65536 = STEPS*HID
    ((uint*)g_h1)[i] = SENT;
    ((uint*)g_h2)[i] = SENT;
}

__device__ __forceinline__ float sigf(float x)     { return 1.0f / (1.0f + __expf(-x)); }
__device__ __forceinline__ float tanhfast(float x) { return 2.0f / (1.0f + __expf(-2.0f * x)) - 1.0f; }

__device__ __forceinline__ ull fma2(ull a, ull b, ull c) {
    ull d;
    asm("fma.rn.f32x2 %0, %1, %2, %3;" : "=l"(d) : "l"(a), "l"(b), "l"(c));
    return d;
}
__device__ __forceinline__ float2 unpack2(ull v) {
    float2 f;
    asm("mov.b64 {%0, %1}, %2;" : "=f"(f.x), "=f"(f.y) : "l"(v));
    return f;
}
__device__ __forceinline__ ull bcast2(float f) {
    ull r;
    asm("mov.b64 %0, {%1, %1};" : "=l"(r) : "f"(f));
    return r;
}
// morally-strong relaxed atomics (gpu scope) for the racing h exchange
__device__ __forceinline__ ull ld_relaxed_b64(const ull* p) {
    ull v;
    asm volatile("ld.relaxed.gpu.global.b64 %0, [%1];" : "=l"(v) : "l"(p) : "memory");
    return v;
}
__device__ __forceinline__ void st_relaxed_f32(float* p, float v) {
    asm volatile("st.relaxed.gpu.global.f32 [%0], %1;" :: "l"(p), "f"(v) : "memory");
}

// ============================================================
// K-split (x16) tiled GEMM — single-shot chunk load (MLP=12),
// ONE syncthreads, then uninterrupted 64-k FMA loop.
//   mode 0: X = x[:,255,:] (stride T*D), rows=4096 -> g_xgp   grid 2048
//   mode 1: X = g_h1,                    rows=4096 -> g_xgp   grid 2048
//   mode 2: X = g_h2,                    rows=512  -> g_zp    grid 256
// 128 threads, 32-row x 64-s tile, thread tile 4x4, f32x2 FMA.
// ============================================================
__global__ __launch_bounds__(128)
void gemmss_k(int mode, const float* __restrict__ xin, const float* __restrict__ W)
{
    __shared__ __align__(16) float Ws[KC][36];   // [k][row]  9.2KB
    __shared__ __align__(16) float Xs[KC][68];   // [k][s]   17.4KB

    const float* X;
    long xbase, xstride;
    float* pout;
    int nrows, ntiles;
    if (mode == 0)      { X = xin;  xbase = 255L * DD; xstride = (long)TT * DD; pout = g_xgp; nrows = G4;  ntiles = 128; }
    else if (mode == 1) { X = g_h1; xbase = 0;         xstride = HID;           pout = g_xgp; nrows = G4;  ntiles = 128; }
    else                { X = g_h2; xbase = 0;         xstride = HID;           pout = g_zp;  nrows = 512; ntiles = 16;  }

    const int chunk = blockIdx.x / ntiles;
    const int rb    = (blockIdx.x % ntiles) * 32;
    pout += (long)chunk * STEPS * nrows;

    const int t  = threadIdx.x;
    const int tr = t >> 4;
    const int tc = t & 15;
    const int k0 = chunk * KC;

    // ---- issue ALL chunk loads up front (12 independent float4/thread) ----
    // W chunk: 32 rows x 64 k = 512 float4, 4/thread
    float4 wbuf[4];
#pragma unroll
    for (int i = 0; i < 4; i++) {
        int f   = t + i * 128;
        int row = f >> 4;            // 16 float4 per row
        int kq  = (f & 15) * 4;
        wbuf[i] = *(const float4*)&W[(long)(rb + row) * 1024 + k0 + kq];
    }
    // X chunk: 64 s x 64 k = 1024 float4, 8/thread
    float4 xbuf[8];
#pragma unroll
    for (int i = 0; i < 8; i++) {
        int f  = t + i * 128;
        int s  = f >> 4;
        int kq = (f & 15) * 4;
        xbuf[i] = *(const float4*)&X[xbase + (long)s * xstride + k0 + kq];
    }
    // ---- transpose into smem ----
#pragma unroll
    for (int i = 0; i < 4; i++) {
        int f   = t + i * 128;
        int row = f >> 4;
        int kq  = (f & 15) * 4;
        Ws[kq + 0][row] = wbuf[i].x;
        Ws[kq + 1][row] = wbuf[i].y;
        Ws[kq + 2][row] = wbuf[i].z;
        Ws[kq + 3][row] = wbuf[i].w;
    }
#pragma unroll
    for (int i = 0; i < 8; i++) {
        int f  = t + i * 128;
        int s  = f >> 4;
        int kq = (f & 15) * 4;
        Xs[kq + 0][s] = xbuf[i].x;
        Xs[kq + 1][s] = xbuf[i].y;
        Xs[kq + 2][s] = xbuf[i].z;
        Xs[kq + 3][s] = xbuf[i].w;
    }
    __syncthreads();   // the ONLY sync

    // ---- 64-k FMA loop, packed f32x2 ----
    ull acc2[4][2];
#pragma unroll
    for (int i = 0; i < 4; i++) { acc2[i][0] = 0ull; acc2[i][1] = 0ull; }

#pragma unroll 16
    for (int k = 0; k < KC; k++) {
        float4 wv = *(const float4*)&Ws[k][tr * 4];
        ull xp0 = *(const ull*)&Xs[k][tc * 4];
        ull xp1 = *(const ull*)&Xs[k][tc * 4 + 2];
        ull wb0 = bcast2(wv.x), wb1 = bcast2(wv.y);
        ull wb2 = bcast2(wv.z), wb3 = bcast2(wv.w);
        acc2[0][0] = fma2(wb0, xp0, acc2[0][0]);
        acc2[0][1] = fma2(wb0, xp1, acc2[0][1]);
        acc2[1][0] = fma2(wb1, xp0, acc2[1][0]);
        acc2[1][1] = fma2(wb1, xp1, acc2[1][1]);
        acc2[2][0] = fma2(wb2, xp0, acc2[2][0]);
        acc2[2][1] = fma2(wb2, xp1, acc2[2][1]);
        acc2[3][0] = fma2(wb3, xp0, acc2[3][0]);
        acc2[3][1] = fma2(wb3, xp1, acc2[3][1]);
    }

#pragma unroll
    for (int i = 0; i < 4; i++) {
        int row = rb + tr * 4 + i;
#pragma unroll
        for (int jp = 0; jp < 2; jp++) {
            float2 v = unpack2(acc2[i][jp]);
            pout[(long)(tc * 4 + jp * 2 + 0) * nrows + row] = v.x;
            pout[(long)(tc * 4 + jp * 2 + 1) * nrows + row] = v.y;
        }
    }
}

// ============================================================
// Persistent LSTM recurrence (VERBATIM from R8 — proven).
// 128 CTAs x 512 threads (16 warps), Whh in packed-f32x2 registers,
// h exchange via sentinel-polled relaxed b64 atomics, 2 syncs/step.
// ============================================================
__global__ __launch_bounds__(512, 1)
void lstm_rec(const float* __restrict__ Whh,
              const float* __restrict__ ba, const float* __restrict__ bb,
              int layer)
{
    __shared__ __align__(16) float hsh[HID];
    __shared__ float graw[32];   // [unit*4 + gate]
    __shared__ float gact[32];

    float* hseq = layer ? g_h2 : g_h1;
    const int r    = blockIdx.x;
    const int t    = threadIdx.x;
    const int lane = t & 31;
    const int w    = t >> 5;       // 0..15
    const int g    = w & 3;
    const int jh   = w >> 2;       // 0..3
    const int rowbase = (g << 10) + (r << 3) + (jh << 1);   // 2 rows

    ull w0[16], w1[16];
#pragma unroll
    for (int p = 0; p < 16; p++) {
        long o = (long)rowbase * 1024 + p * 64 + lane * 2;
        w0[p] = *(const ull*)(Whh + o);
        w1[p] = *(const ull*)(Whh + o + 1024);
    }
    float2 bias = make_float2(0.f, 0.f);
    if (lane == 16) {
        bias.x = ba[rowbase]     + bb[rowbase];
        bias.y = ba[rowbase + 1] + bb[rowbase + 1];
    }
    float creg = 0.0f;   // cell state (warp 0, lanes < 8)
    __syncthreads();

    for (int s = 0; s < STEPS; s++) {
        // xg partials: lanes 0..15 each load one chunk's float2 (summed via
        // the shuffle reduce below); lane 16 contributes the bias.
        float2 part = make_float2(0.f, 0.f);
        if (lane < NCH)
            part = *(const float2*)&g_xgp[(long)lane * STEPS * G4 + (long)s * G4 + rowbase];
        else if (lane == 16)
            part = bias;

        float a0 = part.x, a1 = part.y;
        if (s > 0) {
            // poll h_{s-1}: one relaxed b64 per thread; data itself is the flag
            const ull* src = (const ull*)(hseq + (s - 1) * HID) + t;
            ull hv;
            uint2 u;
            do {
                hv = ld_relaxed_b64(src);
                u  = *(uint2*)&hv;
            } while (u.x == SENT || u.y == SENT);
            ((ull*)hsh)[t] = hv;
            __syncthreads();   // staging sync

            ull acc0 = 0ull, acc1 = 0ull;
#pragma unroll
            for (int p = 0; p < 16; p++) {
                ull h2 = *(const ull*)&hsh[p * 64 + lane * 2];
                acc0 = fma2(w0[p], h2, acc0);
                acc1 = fma2(w1[p], h2, acc1);
            }
            float2 f0 = unpack2(acc0), f1 = unpack2(acc1);
            a0 += f0.x + f0.y;
            a1 += f1.x + f1.y;
        }
#pragma unroll
        for (int o = 16; o > 0; o >>= 1) {
            a0 += __shfl_down_sync(0xffffffffu, a0, o);
            a1 += __shfl_down_sync(0xffffffffu, a1, o);
        }
        if (lane == 0) {
            graw[(jh * 2 + 0) * 4 + g] = a0;
            graw[(jh * 2 + 1) * 4 + g] = a1;
        }
        __syncthreads();   // (A)

        if (w == 0) {
            float v = graw[lane];                       // lane = unit*4 + gate
            gact[lane] = ((lane & 3) == 2) ? tanhfast(v) : sigf(v);
            __syncwarp();
            if (lane < 8) {
                float iv = gact[lane * 4 + 0];
                float fv = gact[lane * 4 + 1];
                float gv = gact[lane * 4 + 2];
                float ov = gact[lane * 4 + 3];
                creg = fmaf(fv, creg, iv * gv);
                st_relaxed_f32(&hseq[s * HID + r * 8 + lane], ov * tanhfast(creg));
            }
        }
        // no end-of-step sync (ordering via poll-gating; proven in R8)
    }
}

// ============================================================
// FC2 fused with fc1 partial-reduce + bias + ReLU. One CTA per s.
// ============================================================
__global__ __launch_bounds__(128)
void fc2_k(const float* __restrict__ W2, const float* __restrict__ b2,
           const float* __restrict__ b1, float* __restrict__ out)
{
    __shared__ __align__(16) float zsh[512];
    const int s = blockIdx.x;
    const int t = threadIdx.x, lane = t & 31, w = t >> 5;

    {
        const long base = (long)s * 512 + t * 4;
        float4 z = *(const float4*)&b1[t * 4];
#pragma unroll
        for (int c = 0; c < NCH; c++) {
            float4 p = *(const float4*)&g_zp[base + (long)c * STEPS * 512];
            z.x += p.x; z.y += p.y; z.z += p.z; z.w += p.w;
        }
        z.x = fmaxf(z.x, 0.f); z.y = fmaxf(z.y, 0.f);
        z.z = fmaxf(z.z, 0.f); z.w = fmaxf(z.w, 0.f);
        *(float4*)&zsh[t * 4] = z;
    }
    __syncthreads();

    for (int c = w; c < CC; c += 4) {
        float acc = 0.f;
#pragma unroll
        for (int k = 0; k < 16; k++)
            acc = fmaf(zsh[k * 32 + lane], W2[c * 512 + k * 32 + lane], acc);
#pragma unroll
        for (int o = 16; o > 0; o >>= 1)
            acc += __shfl_down_sync(0xffffffffu, acc, o);
        if (lane == 0) out[s * CC + c] = acc + b2[c];
    }
}

// ============================================================
extern "C" void kernel_launch(void* const* d_in, const int* in_sizes, int n_in,
                              void* d_out, int out_size)
{
    const float* x    = (const float*)d_in[0];
    const float* Wih0 = (const float*)d_in[1];
    const float* Whh0 = (const float*)d_in[2];
    const float* bih0 = (const float*)d_in[3];
    const float* bhh0 = (const float*)d_in[4];
    const float* Wih1 = (const float*)d_in[5];
    const float* Whh1 = (const float*)d_in[6];
    const float* bih1 = (const float*)d_in[7];
    const float* bhh1 = (const float*)d_in[8];
    const float* W1   = (const float*)d_in[9];
    const float* b1   = (const float*)d_in[10];
    const float* W2   = (const float*)d_in[11];
    const float* b2   = (const float*)d_in[12];
    float* out = (float*)d_out;

    reset_kernel<<<256, 256>>>();                    // sentinel-fill h buffers
    gemmss_k<<<128 * NCH, 128>>>(0, x, Wih0);        // xg partials, layer 1
    lstm_rec<<<NB, 512>>>(Whh0, bih0, bhh0, 0);
    gemmss_k<<<128 * NCH, 128>>>(1, nullptr, Wih1);  // xg partials, layer 2
    lstm_rec<<<NB, 512>>>(Whh1, bih1, bhh1, 1);
    gemmss_k<<<16 * NCH, 128>>>(2, nullptr, W1);     // fc1 partials
    fc2_k<<<64, 128>>>(W2, b2, b1, out);             // reduce+relu+fc2
}

// round 11
// speedup vs baseline: 1.1763x; 1.1066x over previous
#include <cuda_runtime.h>

// Shapes: seq=64 steps (orig B), only batch-row t=255 of T=256 matters.
#define STEPS 64
#define HID   1024
#define G4    4096
#define TT    256
#define DD    1024
#define CC    27
#define NB    128          // recurrence CTAs (1/SM, co-resident)
#define NCH   8            // GEMM K-split chunks
#define KC    128          // k per chunk
#define SENT  0xFFC0DEADu  // NaN payload: impossible LSTM output bit pattern

typedef unsigned long long ull;
typedef unsigned int uint;

// ---- scratch (device globals; no allocation) ----
__device__ __align__(16) float g_xgp[(long)NCH * STEPS * G4];  // gate-preact partials
__device__ __align__(16) float g_h1 [STEPS * HID];
__device__ __align__(16) float g_h2 [STEPS * HID];
__device__ __align__(16) float g_zp [NCH * STEPS * 512];       // fc1 partials

__global__ void reset_kernel() {
    int i = blockIdx.x * 256 + threadIdx.x;   // 256x256 = 65536 = STEPS*HID
    ((uint*)g_h1)[i] = SENT;
    ((uint*)g_h2)[i] = SENT;
}

__device__ __forceinline__ float sigf(float x)     { return 1.0f / (1.0f + __expf(-x)); }
__device__ __forceinline__ float tanhfast(float x) { return 2.0f / (1.0f + __expf(-2.0f * x)) - 1.0f; }

__device__ __forceinline__ ull fma2(ull a, ull b, ull c) {
    ull d;
    asm("fma.rn.f32x2 %0, %1, %2, %3;" : "=l"(d) : "l"(a), "l"(b), "l"(c));
    return d;
}
__device__ __forceinline__ float2 unpack2(ull v) {
    float2 f;
    asm("mov.b64 {%0, %1}, %2;" : "=f"(f.x), "=f"(f.y) : "l"(v));
    return f;
}
// morally-strong relaxed atomics (gpu scope) for the racing h exchange
__device__ __forceinline__ ull ld_relaxed_b64(const ull* p) {
    ull v;
    asm volatile("ld.relaxed.gpu.global.b64 %0, [%1];" : "=l"(v) : "l"(p) : "memory");
    return v;
}
__device__ __forceinline__ void st_relaxed_f32(float* p, float v) {
    asm volatile("st.relaxed.gpu.global.f32 [%0], %1;" :: "l"(p), "f"(v) : "memory");
}

// ============================================================
// K-split (x8) tiled GEMM with 1-tile register prefetch.
// R7 structure (KC=128, 32-k tiles) + software pipeline:
// load tile i+1 (6 float4 regs) during tile i's FMA loop.
//   mode 0: X = x[:,255,:] (stride T*D), rows=4096 -> g_xgp   grid 1024
//   mode 1: X = g_h1,                    rows=4096 -> g_xgp   grid 1024
//   mode 2: X = g_h2,                    rows=512  -> g_zp    grid 128
// ============================================================
__global__ __launch_bounds__(128)
void gemm8p_k(int mode, const float* __restrict__ xin, const float* __restrict__ W)
{
    __shared__ __align__(16) float Ws[32][36];
    __shared__ __align__(16) float Xs[32][68];

    const float* X;
    long xbase, xstride;
    float* pout;
    int nrows, ntiles;
    if (mode == 0)      { X = xin;  xbase = 255L * DD; xstride = (long)TT * DD; pout = g_xgp; nrows = G4;  ntiles = 128; }
    else if (mode == 1) { X = g_h1; xbase = 0;         xstride = HID;           pout = g_xgp; nrows = G4;  ntiles = 128; }
    else                { X = g_h2; xbase = 0;         xstride = HID;           pout = g_zp;  nrows = 512; ntiles = 16;  }

    const int chunk = blockIdx.x / ntiles;
    const int rb    = (blockIdx.x % ntiles) * 32;
    pout += (long)chunk * STEPS * nrows;

    const int t  = threadIdx.x;
    const int tr = t >> 4;
    const int tc = t & 15;
    const int k0 = chunk * KC;

    // per-thread load coordinates (fixed across tiles)
    const int wrow0 = t >> 3,          wkq0 = (t & 7) * 4;            // W lo half
    const int wrow1 = (t + 128) >> 3,  wkq1 = ((t + 128) & 7) * 4;    // W hi half
    int xs_s [4], xs_kq[4];
#pragma unroll
    for (int i = 0; i < 4; i++) { int e = t + i * 128; xs_s[i] = e >> 3; xs_kq[i] = (e & 7) * 4; }

    float4 wA, wB, xA[4];   // prefetch buffer: 6 float4 = 24 regs

    // prologue: load tile 0
    {
        const int kt = k0;
        wA = *(const float4*)&W[(long)(rb + wrow0) * 1024 + kt + wkq0];
        wB = *(const float4*)&W[(long)(rb + wrow1) * 1024 + kt + wkq1];
#pragma unroll
        for (int i = 0; i < 4; i++)
            xA[i] = *(const float4*)&X[xbase + (long)xs_s[i] * xstride + kt + xs_kq[i]];
    }

    float acc[4][4];
#pragma unroll
    for (int i = 0; i < 4; i++)
#pragma unroll
        for (int j = 0; j < 4; j++) acc[i][j] = 0.0f;

#pragma unroll
    for (int tile = 0; tile < 4; tile++) {
        // commit prefetched tile to smem
        Ws[wkq0 + 0][wrow0] = wA.x;
        Ws[wkq0 + 1][wrow0] = wA.y;
        Ws[wkq0 + 2][wrow0] = wA.z;
        Ws[wkq0 + 3][wrow0] = wA.w;
        Ws[wkq1 + 0][wrow1] = wB.x;
        Ws[wkq1 + 1][wrow1] = wB.y;
        Ws[wkq1 + 2][wrow1] = wB.z;
        Ws[wkq1 + 3][wrow1] = wB.w;
#pragma unroll
        for (int i = 0; i < 4; i++) {
            Xs[xs_kq[i] + 0][xs_s[i]] = xA[i].x;
            Xs[xs_kq[i] + 1][xs_s[i]] = xA[i].y;
            Xs[xs_kq[i] + 2][xs_s[i]] = xA[i].z;
            Xs[xs_kq[i] + 3][xs_s[i]] = xA[i].w;
        }
        __syncthreads();

        // prefetch NEXT tile (overlaps the FMA loop below)
        if (tile < 3) {
            const int kt = k0 + (tile + 1) * 32;
            wA = *(const float4*)&W[(long)(rb + wrow0) * 1024 + kt + wkq0];
            wB = *(const float4*)&W[(long)(rb + wrow1) * 1024 + kt + wkq1];
#pragma unroll
            for (int i = 0; i < 4; i++)
                xA[i] = *(const float4*)&X[xbase + (long)xs_s[i] * xstride + kt + xs_kq[i]];
        }

#pragma unroll
        for (int k = 0; k < 32; k++) {
            float4 wv = *(const float4*)&Ws[k][tr * 4];
            float4 xv = *(const float4*)&Xs[k][tc * 4];
            acc[0][0] = fmaf(wv.x, xv.x, acc[0][0]);
            acc[0][1] = fmaf(wv.x, xv.y, acc[0][1]);
            acc[0][2] = fmaf(wv.x, xv.z, acc[0][2]);
            acc[0][3] = fmaf(wv.x, xv.w, acc[0][3]);
            acc[1][0] = fmaf(wv.y, xv.x, acc[1][0]);
            acc[1][1] = fmaf(wv.y, xv.y, acc[1][1]);
            acc[1][2] = fmaf(wv.y, xv.z, acc[1][2]);
            acc[1][3] = fmaf(wv.y, xv.w, acc[1][3]);
            acc[2][0] = fmaf(wv.z, xv.x, acc[2][0]);
            acc[2][1] = fmaf(wv.z, xv.y, acc[2][1]);
            acc[2][2] = fmaf(wv.z, xv.z, acc[2][2]);
            acc[2][3] = fmaf(wv.z, xv.w, acc[2][3]);
            acc[3][0] = fmaf(wv.w, xv.x, acc[3][0]);
            acc[3][1] = fmaf(wv.w, xv.y, acc[3][1]);
            acc[3][2] = fmaf(wv.w, xv.z, acc[3][2]);
            acc[3][3] = fmaf(wv.w, xv.w, acc[3][3]);
        }
        __syncthreads();
    }

#pragma unroll
    for (int i = 0; i < 4; i++) {
        int row = rb + tr * 4 + i;
#pragma unroll
        for (int j = 0; j < 4; j++)
            pout[(long)(tc * 4 + j) * nrows + row] = acc[i][j];
    }
}

// ============================================================
// Persistent LSTM recurrence (VERBATIM from R8 — proven; NCH=8 indexing).
// 128 CTAs x 512 threads (16 warps), Whh in packed-f32x2 registers,
// h exchange via sentinel-polled relaxed b64 atomics, 2 syncs/step.
// ============================================================
__global__ __launch_bounds__(512, 1)
void lstm_rec(const float* __restrict__ Whh,
              const float* __restrict__ ba, const float* __restrict__ bb,
              int layer)
{
    __shared__ __align__(16) float hsh[HID];
    __shared__ float graw[32];   // [unit*4 + gate]
    __shared__ float gact[32];

    float* hseq = layer ? g_h2 : g_h1;
    const int r    = blockIdx.x;
    const int t    = threadIdx.x;
    const int lane = t & 31;
    const int w    = t >> 5;       // 0..15
    const int g    = w & 3;
    const int jh   = w >> 2;       // 0..3
    const int rowbase = (g << 10) + (r << 3) + (jh << 1);   // 2 rows

    ull w0[16], w1[16];
#pragma unroll
    for (int p = 0; p < 16; p++) {
        long o = (long)rowbase * 1024 + p * 64 + lane * 2;
        w0[p] = *(const ull*)(Whh + o);
        w1[p] = *(const ull*)(Whh + o + 1024);
    }
    float2 bias = make_float2(0.f, 0.f);
    if (lane == 16) {
        bias.x = ba[rowbase]     + bb[rowbase];
        bias.y = ba[rowbase + 1] + bb[rowbase + 1];
    }
    float creg = 0.0f;   // cell state (warp 0, lanes < 8)
    __syncthreads();

    for (int s = 0; s < STEPS; s++) {
        // xg partials: lanes 0..7 each load one chunk's float2 (summed via
        // the shuffle reduce below); lane 16 contributes the bias.
        float2 part = make_float2(0.f, 0.f);
        if (lane < NCH)
            part = *(const float2*)&g_xgp[(long)lane * STEPS * G4 + (long)s * G4 + rowbase];
        else if (lane == 16)
            part = bias;

        float a0 = part.x, a1 = part.y;
        if (s > 0) {
            // poll h_{s-1}: one relaxed b64 per thread; data itself is the flag
            const ull* src = (const ull*)(hseq + (s - 1) * HID) + t;
            ull hv;
            uint2 u;
            do {
                hv = ld_relaxed_b64(src);
                u  = *(uint2*)&hv;
            } while (u.x == SENT || u.y == SENT);
            ((ull*)hsh)[t] = hv;
            __syncthreads();   // staging sync

            ull acc0 = 0ull, acc1 = 0ull;
#pragma unroll
            for (int p = 0; p < 16; p++) {
                ull h2 = *(const ull*)&hsh[p * 64 + lane * 2];
                acc0 = fma2(w0[p], h2, acc0);
                acc1 = fma2(w1[p], h2, acc1);
            }
            float2 f0 = unpack2(acc0), f1 = unpack2(acc1);
            a0 += f0.x + f0.y;
            a1 += f1.x + f1.y;
        }
#pragma unroll
        for (int o = 16; o > 0; o >>= 1) {
            a0 += __shfl_down_sync(0xffffffffu, a0, o);
            a1 += __shfl_down_sync(0xffffffffu, a1, o);
        }
        if (lane == 0) {
            graw[(jh * 2 + 0) * 4 + g] = a0;
            graw[(jh * 2 + 1) * 4 + g] = a1;
        }
        __syncthreads();   // (A)

        if (w == 0) {
            float v = graw[lane];                       // lane = unit*4 + gate
            gact[lane] = ((lane & 3) == 2) ? tanhfast(v) : sigf(v);
            __syncwarp();
            if (lane < 8) {
                float iv = gact[lane * 4 + 0];
                float fv = gact[lane * 4 + 1];
                float gv = gact[lane * 4 + 2];
                float ov = gact[lane * 4 + 3];
                creg = fmaf(fv, creg, iv * gv);
                st_relaxed_f32(&hseq[s * HID + r * 8 + lane], ov * tanhfast(creg));
            }
        }
        // no end-of-step sync (ordering via poll-gating; proven in R8)
    }
}

// ============================================================
// FC2 fused with fc1 partial-reduce + bias + ReLU. One CTA per s.
// ============================================================
__global__ __launch_bounds__(128)
void fc2_k(const float* __restrict__ W2, const float* __restrict__ b2,
           const float* __restrict__ b1, float* __restrict__ out)
{
    __shared__ __align__(16) float zsh[512];
    const int s = blockIdx.x;
    const int t = threadIdx.x, lane = t & 31, w = t >> 5;

    {
        const long base = (long)s * 512 + t * 4;
        float4 z = *(const float4*)&b1[t * 4];
#pragma unroll
        for (int c = 0; c < NCH; c++) {
            float4 p = *(const float4*)&g_zp[base + (long)c * STEPS * 512];
            z.x += p.x; z.y += p.y; z.z += p.z; z.w += p.w;
        }
        z.x = fmaxf(z.x, 0.f); z.y = fmaxf(z.y, 0.f);
        z.z = fmaxf(z.z, 0.f); z.w = fmaxf(z.w, 0.f);
        *(float4*)&zsh[t * 4] = z;
    }
    __syncthreads();

    for (int c = w; c < CC; c += 4) {
        float acc = 0.f;
#pragma unroll
        for (int k = 0; k < 16; k++)
            acc = fmaf(zsh[k * 32 + lane], W2[c * 512 + k * 32 + lane], acc);
#pragma unroll
        for (int o = 16; o > 0; o >>= 1)
            acc += __shfl_down_sync(0xffffffffu, acc, o);
        if (lane == 0) out[s * CC + c] = acc + b2[c];
    }
}

// ============================================================
extern "C" void kernel_launch(void* const* d_in, const int* in_sizes, int n_in,
                              void* d_out, int out_size)
{
    const float* x    = (const float*)d_in[0];
    const float* Wih0 = (const float*)d_in[1];
    const float* Whh0 = (const float*)d_in[2];
    const float* bih0 = (const float*)d_in[3];
    const float* bhh0 = (const float*)d_in[4];
    const float* Wih1 = (const float*)d_in[5];
    const float* Whh1 = (const float*)d_in[6];
    const float* bih1 = (const float*)d_in[7];
    const float* bhh1 = (const float*)d_in[8];
    const float* W1   = (const float*)d_in[9];
    const float* b1   = (const float*)d_in[10];
    const float* W2   = (const float*)d_in[11];
    const float* b2   = (const float*)d_in[12];
    float* out = (float*)d_out;

    reset_kernel<<<256, 256>>>();                    // sentinel-fill h buffers
    gemm8p_k<<<128 * NCH, 128>>>(0, x, Wih0);        // xg partials, layer 1
    lstm_rec<<<NB, 512>>>(Whh0, bih0, bhh0, 0);
    gemm8p_k<<<128 * NCH, 128>>>(1, nullptr, Wih1);  // xg partials, layer 2
    lstm_rec<<<NB, 512>>>(Whh1, bih1, bhh1, 1);
    gemm8p_k<<<16 * NCH, 128>>>(2, nullptr, W1);     // fc1 partials
    fc2_k<<<64, 128>>>(W2, b2, b1, out);             // reduce+relu+fc2
}